// round 11
// baseline (speedup 1.0000x reference)
#include <cuda_runtime.h>
#include <cuda_fp16.h>
#include <cstdint>

#define THREADS 256
#define DEG     16
#define DD      128
#define NPB     128     // nodes per block
#define MAXN    100096

// smem: single fp16 A tile, XOR-swizzled rows of 256B
#define SM_A     0
#define SM_TOTAL 32768

// W in mma-B-fragment layout, fp16 hi/lo interleaved
__device__ uint4 gB[8 * 128 * 4];
// fp16 node features (25.6 MB), row = 16 uint4
__device__ uint4 gFeat16[MAXN * DD / 8];
// packed normalized edges: {col, w/den} per edge (12.8 MB)
__device__ uint2 gEdgeP[MAXN * DEG];

__device__ __forceinline__ void split_f16(float x, unsigned short& h, unsigned short& l) {
    __half hh = __float2half_rn(x);
    float r = x - __half2float(hh);
    __half ll = __float2half_rn(r);
    h = __half_as_ushort(hh);
    l = __half_as_ushort(ll);
}

__device__ __forceinline__ int a_off(int row, int chunk) {
    return row * 256 + ((chunk ^ (row & 7)) << 4);
}

__device__ __forceinline__ uint32_t smem_u32(const void* p) {
    uint32_t a;
    asm("{ .reg .u64 t; cvta.to.shared.u64 t, %1; cvt.u32.u64 %0, t; }" : "=r"(a) : "l"(p));
    return a;
}

__device__ __forceinline__ void ldmatrix_x4(uint32_t& r0, uint32_t& r1,
                                            uint32_t& r2, uint32_t& r3, uint32_t addr) {
    asm volatile("ldmatrix.sync.aligned.m8n8.x4.shared.b16 {%0,%1,%2,%3}, [%4];"
                 : "=r"(r0), "=r"(r1), "=r"(r2), "=r"(r3) : "r"(addr));
}

__device__ __forceinline__ void mma_f16(float& d0, float& d1, float& d2, float& d3,
                                        uint32_t a0, uint32_t a1, uint32_t a2, uint32_t a3,
                                        uint32_t b0, uint32_t b1) {
    asm volatile("mma.sync.aligned.m16n8k16.row.col.f32.f16.f16.f32 "
                 "{%0,%1,%2,%3}, {%4,%5,%6,%7}, {%8,%9}, {%0,%1,%2,%3};"
                 : "+f"(d0), "+f"(d1), "+f"(d2), "+f"(d3)
                 : "r"(a0), "r"(a1), "r"(a2), "r"(a3), "r"(b0), "r"(b1));
}

__device__ __forceinline__ void fma2_h2(unsigned long long& acc,
                                        unsigned long long w2, unsigned h2bits) {
    const float2 f = __half22float2(*(const __half2*)&h2bits);
    unsigned long long v;
    asm("mov.b64 %0, {%1, %2};" : "=l"(v) : "f"(f.x), "f"(f.y));
    asm("fma.rn.f32x2 %0, %1, %2, %0;" : "+l"(acc) : "l"(w2), "l"(v));
}
__device__ __forceinline__ void unpack64(unsigned long long v, float& lo, float& hi) {
    asm("mov.b64 {%0, %1}, %2;" : "=f"(lo), "=f"(hi) : "l"(v));
}

// ---- fused prep: feat fp32->fp16 | W fp16-split | coalesced edge packing ----
__global__ void __launch_bounds__(256)
prep_all(const float* __restrict__ feat, const float* __restrict__ Wg,
         const int* __restrict__ rows32, const char* __restrict__ cols_raw,
         const float* __restrict__ ew,
         int nblk_feat, int nblk_w, int total16, int N)
{
    const int b = (int)blockIdx.x;
    if (b < nblk_feat) {
        const int i = b * 256 + threadIdx.x;             // unit = 16 floats
        if (i >= total16) return;
        const float4* src = (const float4*)feat + i * 4;
        uint4* dst = gFeat16 + i * 2;
        float4 v0 = __ldg(src + 0);
        float4 v1 = __ldg(src + 1);
        float4 v2 = __ldg(src + 2);
        float4 v3 = __ldg(src + 3);
        __half2 a0 = __floats2half2_rn(v0.x, v0.y), a1 = __floats2half2_rn(v0.z, v0.w);
        __half2 a2 = __floats2half2_rn(v1.x, v1.y), a3 = __floats2half2_rn(v1.z, v1.w);
        __half2 a4 = __floats2half2_rn(v2.x, v2.y), a5 = __floats2half2_rn(v2.z, v2.w);
        __half2 a6 = __floats2half2_rn(v3.x, v3.y), a7 = __floats2half2_rn(v3.z, v3.w);
        dst[0] = make_uint4(*(unsigned*)&a0, *(unsigned*)&a1, *(unsigned*)&a2, *(unsigned*)&a3);
        dst[1] = make_uint4(*(unsigned*)&a4, *(unsigned*)&a5, *(unsigned*)&a6, *(unsigned*)&a7);
    } else if (b < nblk_feat + nblk_w) {
        const int e = (b - nblk_feat) * 256 + threadIdx.x;   // 0..4095
        if (e >= 8 * 128 * 4) return;
        const int kc = e >> 9;
        const int n  = (e >> 2) & 127;
        const int q  = e & 3;
        const int k0 = kc * 16 + 2 * q;
        unsigned short h[4], l[4];
        split_f16(__ldg(Wg + (k0    ) * DD + n), h[0], l[0]);
        split_f16(__ldg(Wg + (k0 + 1) * DD + n), h[1], l[1]);
        split_f16(__ldg(Wg + (k0 + 8) * DD + n), h[2], l[2]);
        split_f16(__ldg(Wg + (k0 + 9) * DD + n), h[3], l[3]);
        gB[e] = make_uint4((unsigned)h[0] | ((unsigned)h[1] << 16),
                           (unsigned)h[2] | ((unsigned)h[3] << 16),
                           (unsigned)l[0] | ((unsigned)l[1] << 16),
                           (unsigned)l[2] | ((unsigned)l[3] << 16));
    } else {
        // edge packing: 64 nodes per block; half-warp per node, lane i = edge i
        const bool idx64 = (__ldg(rows32 + 33) == 0);
        const int li = threadIdx.x & 15;
        #pragma unroll
        for (int j = 0; j < 4; j++) {
            const int node0 = (b - nblk_feat - nblk_w) * 64 + j * 16 + ((int)threadIdx.x >> 4);
            const int node  = min(node0, N - 1);
            const long long ei = (long long)node * DEG + li;
            const int   c = idx64 ? (int)__ldg((const long long*)cols_raw + ei)
                                  : __ldg((const int*)cols_raw + ei);
            const float w = __ldg(ew + ei);
            float den = w;
            den += __shfl_xor_sync(0xffffffffu, den, 1);
            den += __shfl_xor_sync(0xffffffffu, den, 2);
            den += __shfl_xor_sync(0xffffffffu, den, 4);
            den += __shfl_xor_sync(0xffffffffu, den, 8);
            const float wn = w * __fdividef(1.f, den);
            if (node0 < N)
                gEdgeP[(size_t)node * DEG + li] = make_uint2((unsigned)c, __float_as_uint(wn));
        }
    }
}

// ---- fused main: gather (packed edges) -> smem A tile -> HMMA -> bias+relu ----
__global__ void __launch_bounds__(THREADS, 5)
gcn_mma(const float* __restrict__ bias, float* __restrict__ out, int N)
{
    extern __shared__ char smem[];
    const int tid   = threadIdx.x;
    const int wid   = tid >> 5;
    const int lane  = tid & 31;
    const int node0 = blockIdx.x * NPB;

    // ---- Phase 1: mean-aggregate; half-warp per node, lane owns 8 features ----
    const int s  = lane & 15;
    const int hb = lane >> 4;
    #pragma unroll 2
    for (int p = wid; p < NPB / 2; p += 8) {
        const int row = 2 * p + hb;
        const int myn = min(node0 + row, N - 1);     // clamp: OOB rows unused
        const uint2* __restrict__ ep = gEdgeP + (size_t)myn * DEG;

        unsigned long long acc[4] = {0ull, 0ull, 0ull, 0ull};
        #pragma unroll
        for (int e = 0; e < DEG; e++) {
            const uint2 d = __ldg(ep + e);           // {col, w/den} uniform in half-warp
            const uint4 v = __ldg(gFeat16 + (size_t)d.x * 16 + s);
            unsigned long long w2;
            asm("mov.b64 %0, {%1, %1};" : "=l"(w2) : "r"(d.y));
            fma2_h2(acc[0], w2, v.x);
            fma2_h2(acc[1], w2, v.y);
            fma2_h2(acc[2], w2, v.z);
            fma2_h2(acc[3], w2, v.w);
        }

        float f[8];
        unpack64(acc[0], f[0], f[1]);
        unpack64(acc[1], f[2], f[3]);
        unpack64(acc[2], f[4], f[5]);
        unpack64(acc[3], f[6], f[7]);
        const __half2 p0 = __floats2half2_rn(f[0], f[1]);
        const __half2 p1 = __floats2half2_rn(f[2], f[3]);
        const __half2 p2 = __floats2half2_rn(f[4], f[5]);
        const __half2 p3 = __floats2half2_rn(f[6], f[7]);
        *(uint4*)(smem + SM_A + a_off(row, s)) =
            make_uint4(*(const unsigned*)&p0, *(const unsigned*)&p1,
                       *(const unsigned*)&p2, *(const unsigned*)&p3);
    }
    __syncthreads();

    // ---- Phase 2: warp = 16 rows x 128 cols, as four 16x32 quarter-tiles ----
    const int m0 = wid * 16;
    const int mi = lane >> 3;
    const int mr = lane & 7;
    const int arow = m0 + ((mi & 1) << 3) + mr;
    const uint32_t sA = smem_u32(smem + SM_A);
    const int bq = (lane >> 2) * 4 + (lane & 3);

    const int r0 = node0 + m0 + (lane >> 2);
    const int cb = 2 * (lane & 3);

    #pragma unroll
    for (int q = 0; q < 4; q++) {
        float acc[4][4];
        #pragma unroll
        for (int nc = 0; nc < 4; nc++)
            acc[nc][0] = acc[nc][1] = acc[nc][2] = acc[nc][3] = 0.f;

        #pragma unroll
        for (int kc = 0; kc < 8; kc++) {
            const int chunk = kc * 2 + (mi >> 1);
            const uint32_t aaddr = (uint32_t)a_off(arow, chunk);
            uint32_t a0, a1, a2, a3;
            ldmatrix_x4(a0, a1, a2, a3, sA + aaddr);

            const uint4* __restrict__ bp = gB + kc * 512 + q * 128 + bq;
            #pragma unroll
            for (int nc = 0; nc < 4; nc++) {
                const uint4 v = __ldg(bp + nc * 32);
                mma_f16(acc[nc][0], acc[nc][1], acc[nc][2], acc[nc][3],
                        a0, a1, a2, a3, v.x, v.y);
                mma_f16(acc[nc][0], acc[nc][1], acc[nc][2], acc[nc][3],
                        a0, a1, a2, a3, v.z, v.w);
            }
        }

        // ---- epilogue for this quarter: bias + relu + store ----
        #pragma unroll
        for (int nc = 0; nc < 4; nc++) {
            const int col = q * 32 + nc * 8 + cb;
            const float2 bv = __ldg((const float2*)(bias + col));
            if (r0 < N) {
                float2 o0;
                o0.x = fmaxf(acc[nc][0] + bv.x, 0.f);
                o0.y = fmaxf(acc[nc][1] + bv.y, 0.f);
                *(float2*)(out + (size_t)r0 * DD + col) = o0;
            }
            if (r0 + 8 < N) {
                float2 o1;
                o1.x = fmaxf(acc[nc][2] + bv.x, 0.f);
                o1.y = fmaxf(acc[nc][3] + bv.y, 0.f);
                *(float2*)(out + (size_t)(r0 + 8) * DD + col) = o1;
            }
        }
    }
}

extern "C" void kernel_launch(void* const* d_in, const int* in_sizes, int n_in,
                              void* d_out, int out_size)
{
    const float* feat = (const float*)d_in[0];
    const int*   rows = (const int*)d_in[1];
    const char*  cols = (const char*)d_in[2];
    const float* ew   = (const float*)d_in[3];
    const float* Wg   = (const float*)d_in[4];
    const float* bias = (const float*)d_in[5];
    float*       out  = (float*)d_out;

    const int N = in_sizes[0] / DD;

    const int total16   = N * DD / 16;
    const int nblk_feat = (total16 + 255) / 256;
    const int nblk_w    = (8 * 128 * 4 + 255) / 256;
    const int nblk_e    = (N + 63) / 64;
    prep_all<<<nblk_feat + nblk_w + nblk_e, 256>>>(feat, Wg, rows, cols, ew,
                                                   nblk_feat, nblk_w, total16, N);

    cudaFuncSetAttribute(gcn_mma, cudaFuncAttributeMaxDynamicSharedMemorySize, SM_TOTAL);
    gcn_mma<<<(N + NPB - 1) / NPB, THREADS, SM_TOTAL>>>(bias, out, N);
}

// round 12
// speedup vs baseline: 1.4147x; 1.4147x over previous
#include <cuda_runtime.h>
#include <cuda_fp16.h>
#include <cstdint>

#define THREADS 256
#define DEG     16
#define DD      128
#define NPB     128     // nodes per block
#define MAXN    100096

// smem: single fp16 A tile, XOR-swizzled rows of 256B
#define SM_A     0
#define SM_TOTAL 32768

// W in mma-B-fragment layout, fp16 hi/lo interleaved
__device__ uint4 gB[8 * 128 * 4];
// fp16 node features (25.6 MB), row = 16 uint4
__device__ uint4 gFeat16[MAXN * DD / 8];
// packed normalized edges: {col, w/den} per edge (12.8 MB)
__device__ uint2 gEdgeP[MAXN * DEG];

__device__ __forceinline__ void split_f16(float x, unsigned short& h, unsigned short& l) {
    __half hh = __float2half_rn(x);
    float r = x - __half2float(hh);
    __half ll = __float2half_rn(r);
    h = __half_as_ushort(hh);
    l = __half_as_ushort(ll);
}

__device__ __forceinline__ int a_off(int row, int chunk) {
    return row * 256 + ((chunk ^ (row & 7)) << 4);
}

__device__ __forceinline__ uint32_t smem_u32(const void* p) {
    uint32_t a;
    asm("{ .reg .u64 t; cvta.to.shared.u64 t, %1; cvt.u32.u64 %0, t; }" : "=r"(a) : "l"(p));
    return a;
}

__device__ __forceinline__ void ldmatrix_x4(uint32_t& r0, uint32_t& r1,
                                            uint32_t& r2, uint32_t& r3, uint32_t addr) {
    asm volatile("ldmatrix.sync.aligned.m8n8.x4.shared.b16 {%0,%1,%2,%3}, [%4];"
                 : "=r"(r0), "=r"(r1), "=r"(r2), "=r"(r3) : "r"(addr));
}

__device__ __forceinline__ void mma_f16(float& d0, float& d1, float& d2, float& d3,
                                        uint32_t a0, uint32_t a1, uint32_t a2, uint32_t a3,
                                        uint32_t b0, uint32_t b1) {
    asm volatile("mma.sync.aligned.m16n8k16.row.col.f32.f16.f16.f32 "
                 "{%0,%1,%2,%3}, {%4,%5,%6,%7}, {%8,%9}, {%0,%1,%2,%3};"
                 : "+f"(d0), "+f"(d1), "+f"(d2), "+f"(d3)
                 : "r"(a0), "r"(a1), "r"(a2), "r"(a3), "r"(b0), "r"(b1));
}

__device__ __forceinline__ void fma2_h2(unsigned long long& acc,
                                        unsigned long long w2, unsigned h2bits) {
    const float2 f = __half22float2(*(const __half2*)&h2bits);
    unsigned long long v;
    asm("mov.b64 %0, {%1, %2};" : "=l"(v) : "f"(f.x), "f"(f.y));
    asm("fma.rn.f32x2 %0, %1, %2, %0;" : "+l"(acc) : "l"(w2), "l"(v));
}
__device__ __forceinline__ void unpack64(unsigned long long v, float& lo, float& hi) {
    asm("mov.b64 {%0, %1}, %2;" : "=f"(lo), "=f"(hi) : "l"(v));
}

// ---- fused prep: feat fp32->fp16 | W fp16-split | coalesced edge packing ----
__global__ void __launch_bounds__(256)
prep_all(const float* __restrict__ feat, const float* __restrict__ Wg,
         const int* __restrict__ rows32, const char* __restrict__ cols_raw,
         const float* __restrict__ ew,
         int nblk_feat, int nblk_w, int total16, int N)
{
    const int b = (int)blockIdx.x;
    if (b < nblk_feat) {
        const int i = b * 256 + threadIdx.x;             // unit = 16 floats
        if (i >= total16) return;
        const float4* src = (const float4*)feat + i * 4;
        uint4* dst = gFeat16 + i * 2;
        float4 v0 = __ldg(src + 0);
        float4 v1 = __ldg(src + 1);
        float4 v2 = __ldg(src + 2);
        float4 v3 = __ldg(src + 3);
        __half2 a0 = __floats2half2_rn(v0.x, v0.y), a1 = __floats2half2_rn(v0.z, v0.w);
        __half2 a2 = __floats2half2_rn(v1.x, v1.y), a3 = __floats2half2_rn(v1.z, v1.w);
        __half2 a4 = __floats2half2_rn(v2.x, v2.y), a5 = __floats2half2_rn(v2.z, v2.w);
        __half2 a6 = __floats2half2_rn(v3.x, v3.y), a7 = __floats2half2_rn(v3.z, v3.w);
        dst[0] = make_uint4(*(unsigned*)&a0, *(unsigned*)&a1, *(unsigned*)&a2, *(unsigned*)&a3);
        dst[1] = make_uint4(*(unsigned*)&a4, *(unsigned*)&a5, *(unsigned*)&a6, *(unsigned*)&a7);
    } else if (b < nblk_feat + nblk_w) {
        const int e = (b - nblk_feat) * 256 + threadIdx.x;   // 0..4095
        if (e >= 8 * 128 * 4) return;
        const int kc = e >> 9;
        const int n  = (e >> 2) & 127;
        const int q  = e & 3;
        const int k0 = kc * 16 + 2 * q;
        unsigned short h[4], l[4];
        split_f16(__ldg(Wg + (k0    ) * DD + n), h[0], l[0]);
        split_f16(__ldg(Wg + (k0 + 1) * DD + n), h[1], l[1]);
        split_f16(__ldg(Wg + (k0 + 8) * DD + n), h[2], l[2]);
        split_f16(__ldg(Wg + (k0 + 9) * DD + n), h[3], l[3]);
        gB[e] = make_uint4((unsigned)h[0] | ((unsigned)h[1] << 16),
                           (unsigned)h[2] | ((unsigned)h[3] << 16),
                           (unsigned)l[0] | ((unsigned)l[1] << 16),
                           (unsigned)l[2] | ((unsigned)l[3] << 16));
    } else {
        // edge packing: 64 nodes per block; half-warp per node, lane i = edge i
        const bool idx64 = (__ldg(rows32 + 33) == 0);
        const int li = threadIdx.x & 15;
        #pragma unroll
        for (int j = 0; j < 4; j++) {
            const int node0 = (b - nblk_feat - nblk_w) * 64 + j * 16 + ((int)threadIdx.x >> 4);
            const int node  = min(node0, N - 1);
            const long long ei = (long long)node * DEG + li;
            const int   c = idx64 ? (int)__ldg((const long long*)cols_raw + ei)
                                  : __ldg((const int*)cols_raw + ei);
            const float w = __ldg(ew + ei);
            float den = w;
            den += __shfl_xor_sync(0xffffffffu, den, 1);
            den += __shfl_xor_sync(0xffffffffu, den, 2);
            den += __shfl_xor_sync(0xffffffffu, den, 4);
            den += __shfl_xor_sync(0xffffffffu, den, 8);
            const float wn = w * __fdividef(1.f, den);
            if (node0 < N)
                gEdgeP[(size_t)node * DEG + li] = make_uint2((unsigned)c, __float_as_uint(wn));
        }
    }
}

// ---- fused main (R8 structure): gather -> smem A tile -> HMMA -> bias+relu ----
__global__ void __launch_bounds__(THREADS, 4)
gcn_mma(const float* __restrict__ bias, float* __restrict__ out, int N)
{
    extern __shared__ char smem[];
    const int tid   = threadIdx.x;
    const int wid   = tid >> 5;
    const int lane  = tid & 31;
    const int node0 = blockIdx.x * NPB;

    // ---- Phase 1: mean-aggregate; half-warp per node, lane owns 8 features ----
    const int s  = lane & 15;            // feature slice (8 halves = 1 uint4)
    const int hb = lane >> 4;            // 0: node 2p, 1: node 2p+1
    for (int p = wid; p < NPB / 2; p += 8) {
        const int row = 2 * p + hb;
        const int myn = min(node0 + row, N - 1);       // clamp: OOB rows unused
        const uint2* __restrict__ ep = gEdgeP + (size_t)myn * DEG;

        unsigned long long acc[4] = {0ull, 0ull, 0ull, 0ull};
        #pragma unroll
        for (int e = 0; e < DEG; e++) {
            const uint2 d = __ldg(ep + e);             // {col, w/den} uniform in half-warp
            const uint4 v = __ldg(gFeat16 + (size_t)d.x * 16 + s);
            unsigned long long w2;
            asm("mov.b64 %0, {%1, %1};" : "=l"(w2) : "r"(d.y));
            fma2_h2(acc[0], w2, v.x);
            fma2_h2(acc[1], w2, v.y);
            fma2_h2(acc[2], w2, v.z);
            fma2_h2(acc[3], w2, v.w);
        }

        float f[8];
        unpack64(acc[0], f[0], f[1]);
        unpack64(acc[1], f[2], f[3]);
        unpack64(acc[2], f[4], f[5]);
        unpack64(acc[3], f[6], f[7]);
        const __half2 p0 = __floats2half2_rn(f[0], f[1]);
        const __half2 p1 = __floats2half2_rn(f[2], f[3]);
        const __half2 p2 = __floats2half2_rn(f[4], f[5]);
        const __half2 p3 = __floats2half2_rn(f[6], f[7]);

        *(uint4*)(smem + SM_A + a_off(row, s)) =
            make_uint4(*(const unsigned*)&p0, *(const unsigned*)&p1,
                       *(const unsigned*)&p2, *(const unsigned*)&p3);
    }
    __syncthreads();

    // ---- Phase 2: warp = 16 rows x 128 cols, as two 16x64 half-tiles ----
    const int m0 = wid * 16;
    const int mi = lane >> 3;
    const int mr = lane & 7;
    const int arow = m0 + ((mi & 1) << 3) + mr;
    const uint32_t sA = smem_u32(smem + SM_A);
    const int bq = (lane >> 2) * 4 + (lane & 3);

    const int r0 = node0 + m0 + (lane >> 2);
    const int cb = 2 * (lane & 3);

    #pragma unroll
    for (int half = 0; half < 2; half++) {
        float acc[8][4];
        #pragma unroll
        for (int nc = 0; nc < 8; nc++)
            acc[nc][0] = acc[nc][1] = acc[nc][2] = acc[nc][3] = 0.f;

        #pragma unroll
        for (int kc = 0; kc < 8; kc++) {
            const int chunk = kc * 2 + (mi >> 1);
            const uint32_t aaddr = (uint32_t)a_off(arow, chunk);
            uint32_t a0, a1, a2, a3;
            ldmatrix_x4(a0, a1, a2, a3, sA + aaddr);

            const uint4* __restrict__ bp = gB + kc * 512 + half * 256 + bq;
            #pragma unroll
            for (int nc = 0; nc < 8; nc++) {
                const uint4 v = __ldg(bp + nc * 32);
                mma_f16(acc[nc][0], acc[nc][1], acc[nc][2], acc[nc][3],
                        a0, a1, a2, a3, v.x, v.y);
                mma_f16(acc[nc][0], acc[nc][1], acc[nc][2], acc[nc][3],
                        a0, a1, a2, a3, v.z, v.w);
            }
        }

        // ---- epilogue for this half: bias + relu + store ----
        #pragma unroll
        for (int nc = 0; nc < 8; nc++) {
            const int col = half * 64 + nc * 8 + cb;
            const float2 bv = __ldg((const float2*)(bias + col));
            if (r0 < N) {
                float2 o0;
                o0.x = fmaxf(acc[nc][0] + bv.x, 0.f);
                o0.y = fmaxf(acc[nc][1] + bv.y, 0.f);
                *(float2*)(out + (size_t)r0 * DD + col) = o0;
            }
            if (r0 + 8 < N) {
                float2 o1;
                o1.x = fmaxf(acc[nc][2] + bv.x, 0.f);
                o1.y = fmaxf(acc[nc][3] + bv.y, 0.f);
                *(float2*)(out + (size_t)(r0 + 8) * DD + col) = o1;
            }
        }
    }
}

extern "C" void kernel_launch(void* const* d_in, const int* in_sizes, int n_in,
                              void* d_out, int out_size)
{
    const float* feat = (const float*)d_in[0];
    const int*   rows = (const int*)d_in[1];
    const char*  cols = (const char*)d_in[2];
    const float* ew   = (const float*)d_in[3];
    const float* Wg   = (const float*)d_in[4];
    const float* bias = (const float*)d_in[5];
    float*       out  = (float*)d_out;

    const int N = in_sizes[0] / DD;

    const int total16   = N * DD / 16;
    const int nblk_feat = (total16 + 255) / 256;
    const int nblk_w    = (8 * 128 * 4 + 255) / 256;
    const int nblk_e    = (N + 63) / 64;
    prep_all<<<nblk_feat + nblk_w + nblk_e, 256>>>(feat, Wg, rows, cols, ew,
                                                   nblk_feat, nblk_w, total16, N);

    cudaFuncSetAttribute(gcn_mma, cudaFuncAttributeMaxDynamicSharedMemorySize, SM_TOTAL);
    gcn_mma<<<(N + NPB - 1) / NPB, THREADS, SM_TOTAL>>>(bias, out, N);
}

// round 13
// speedup vs baseline: 1.4295x; 1.0105x over previous
#include <cuda_runtime.h>
#include <cuda_fp16.h>
#include <cstdint>

#define THREADS 256
#define DEG     16
#define DD      128
#define NPB     128     // nodes per block
#define MAXN    100096

// smem: fp16 A tile (32KB, XOR-swizzled 256B rows) + edge-desc slab (16KB)
#define SM_A     0
#define SM_ED    32768
#define SM_TOTAL 49152

// W in mma-B-fragment layout, fp16 hi/lo interleaved
__device__ uint4 gB[8 * 128 * 4];
// fp16 node features (25.6 MB), row = 16 uint4
__device__ uint4 gFeat16[MAXN * DD / 8];
// packed normalized edges: {col, w/den} per edge (12.8 MB), node-major contiguous
__device__ uint2 gEdgeP[MAXN * DEG];

__device__ __forceinline__ void split_f16(float x, unsigned short& h, unsigned short& l) {
    __half hh = __float2half_rn(x);
    float r = x - __half2float(hh);
    __half ll = __float2half_rn(r);
    h = __half_as_ushort(hh);
    l = __half_as_ushort(ll);
}

__device__ __forceinline__ int a_off(int row, int chunk) {
    return row * 256 + ((chunk ^ (row & 7)) << 4);
}

__device__ __forceinline__ uint32_t smem_u32(const void* p) {
    uint32_t a;
    asm("{ .reg .u64 t; cvta.to.shared.u64 t, %1; cvt.u32.u64 %0, t; }" : "=r"(a) : "l"(p));
    return a;
}

__device__ __forceinline__ void cp_async16(void* smem_dst, const void* gsrc) {
    unsigned int s = (unsigned int)__cvta_generic_to_shared(smem_dst);
    asm volatile("cp.async.cg.shared.global [%0], [%1], 16;\n" :: "r"(s), "l"(gsrc));
}

__device__ __forceinline__ void ldmatrix_x4(uint32_t& r0, uint32_t& r1,
                                            uint32_t& r2, uint32_t& r3, uint32_t addr) {
    asm volatile("ldmatrix.sync.aligned.m8n8.x4.shared.b16 {%0,%1,%2,%3}, [%4];"
                 : "=r"(r0), "=r"(r1), "=r"(r2), "=r"(r3) : "r"(addr));
}

__device__ __forceinline__ void mma_f16(float& d0, float& d1, float& d2, float& d3,
                                        uint32_t a0, uint32_t a1, uint32_t a2, uint32_t a3,
                                        uint32_t b0, uint32_t b1) {
    asm volatile("mma.sync.aligned.m16n8k16.row.col.f32.f16.f16.f32 "
                 "{%0,%1,%2,%3}, {%4,%5,%6,%7}, {%8,%9}, {%0,%1,%2,%3};"
                 : "+f"(d0), "+f"(d1), "+f"(d2), "+f"(d3)
                 : "r"(a0), "r"(a1), "r"(a2), "r"(a3), "r"(b0), "r"(b1));
}

__device__ __forceinline__ void fma2_h2(unsigned long long& acc,
                                        unsigned long long w2, unsigned h2bits) {
    const float2 f = __half22float2(*(const __half2*)&h2bits);
    unsigned long long v;
    asm("mov.b64 %0, {%1, %2};" : "=l"(v) : "f"(f.x), "f"(f.y));
    asm("fma.rn.f32x2 %0, %1, %2, %0;" : "+l"(acc) : "l"(w2), "l"(v));
}
__device__ __forceinline__ void unpack64(unsigned long long v, float& lo, float& hi) {
    asm("mov.b64 {%0, %1}, %2;" : "=f"(lo), "=f"(hi) : "l"(v));
}

// ---- fused prep: feat fp32->fp16 | W fp16-split | coalesced edge packing ----
__global__ void __launch_bounds__(256)
prep_all(const float* __restrict__ feat, const float* __restrict__ Wg,
         const int* __restrict__ rows32, const char* __restrict__ cols_raw,
         const float* __restrict__ ew,
         int nblk_feat, int nblk_w, int total16, int N)
{
    const int b = (int)blockIdx.x;
    if (b < nblk_feat) {
        const int i = b * 256 + threadIdx.x;             // unit = 16 floats
        if (i >= total16) return;
        const float4* src = (const float4*)feat + i * 4;
        uint4* dst = gFeat16 + i * 2;
        float4 v0 = __ldg(src + 0);
        float4 v1 = __ldg(src + 1);
        float4 v2 = __ldg(src + 2);
        float4 v3 = __ldg(src + 3);
        __half2 a0 = __floats2half2_rn(v0.x, v0.y), a1 = __floats2half2_rn(v0.z, v0.w);
        __half2 a2 = __floats2half2_rn(v1.x, v1.y), a3 = __floats2half2_rn(v1.z, v1.w);
        __half2 a4 = __floats2half2_rn(v2.x, v2.y), a5 = __floats2half2_rn(v2.z, v2.w);
        __half2 a6 = __floats2half2_rn(v3.x, v3.y), a7 = __floats2half2_rn(v3.z, v3.w);
        dst[0] = make_uint4(*(unsigned*)&a0, *(unsigned*)&a1, *(unsigned*)&a2, *(unsigned*)&a3);
        dst[1] = make_uint4(*(unsigned*)&a4, *(unsigned*)&a5, *(unsigned*)&a6, *(unsigned*)&a7);
    } else if (b < nblk_feat + nblk_w) {
        const int e = (b - nblk_feat) * 256 + threadIdx.x;   // 0..4095
        if (e >= 8 * 128 * 4) return;
        const int kc = e >> 9;
        const int n  = (e >> 2) & 127;
        const int q  = e & 3;
        const int k0 = kc * 16 + 2 * q;
        unsigned short h[4], l[4];
        split_f16(__ldg(Wg + (k0    ) * DD + n), h[0], l[0]);
        split_f16(__ldg(Wg + (k0 + 1) * DD + n), h[1], l[1]);
        split_f16(__ldg(Wg + (k0 + 8) * DD + n), h[2], l[2]);
        split_f16(__ldg(Wg + (k0 + 9) * DD + n), h[3], l[3]);
        gB[e] = make_uint4((unsigned)h[0] | ((unsigned)h[1] << 16),
                           (unsigned)h[2] | ((unsigned)h[3] << 16),
                           (unsigned)l[0] | ((unsigned)l[1] << 16),
                           (unsigned)l[2] | ((unsigned)l[3] << 16));
    } else {
        // edge packing: 64 nodes per block; half-warp per node, lane i = edge i
        const bool idx64 = (__ldg(rows32 + 33) == 0);
        const int li = threadIdx.x & 15;
        #pragma unroll
        for (int j = 0; j < 4; j++) {
            const int node0 = (b - nblk_feat - nblk_w) * 64 + j * 16 + ((int)threadIdx.x >> 4);
            const int node  = min(node0, N - 1);
            const long long ei = (long long)node * DEG + li;
            const int   c = idx64 ? (int)__ldg((const long long*)cols_raw + ei)
                                  : __ldg((const int*)cols_raw + ei);
            const float w = __ldg(ew + ei);
            float den = w;
            den += __shfl_xor_sync(0xffffffffu, den, 1);
            den += __shfl_xor_sync(0xffffffffu, den, 2);
            den += __shfl_xor_sync(0xffffffffu, den, 4);
            den += __shfl_xor_sync(0xffffffffu, den, 8);
            const float wn = w * __fdividef(1.f, den);
            if (node0 < N)
                gEdgeP[(size_t)node * DEG + li] = make_uint2((unsigned)c, __float_as_uint(wn));
        }
    }
}

// ---- fused main: cp.async edge slab -> gather -> smem A tile -> HMMA ----
__global__ void __launch_bounds__(THREADS, 4)
gcn_mma(const float* __restrict__ bias, float* __restrict__ out, int N)
{
    extern __shared__ char smem[];
    const int tid   = threadIdx.x;
    const int wid   = tid >> 5;
    const int lane  = tid & 31;
    const int node0 = blockIdx.x * NPB;

    // ---- Prologue: stage this block's 128-node edge-desc slab (16 KB) ----
    {
        const uint2* src = gEdgeP + (size_t)node0 * DEG;   // contiguous 2048 uint2
        #pragma unroll
        for (int i = 0; i < 4; i++) {
            const int idx = i * 256 + tid;                 // 16B units, 0..1023
            cp_async16(smem + SM_ED + idx * 16, src + idx * 2);
        }
        asm volatile("cp.async.commit_group;" ::: "memory");
        asm volatile("cp.async.wait_group 0;" ::: "memory");
    }
    __syncthreads();

    // ---- Phase 1: mean-aggregate; half-warp per node, lane owns 8 features ----
    const int s  = lane & 15;            // feature slice (8 halves = 1 uint4)
    const int hb = lane >> 4;            // 0: node 2p, 1: node 2p+1
    for (int p = wid; p < NPB / 2; p += 8) {
        const int row = 2 * p + hb;
        const uint2* ed = (const uint2*)(smem + SM_ED) + row * DEG;

        unsigned long long acc[4] = {0ull, 0ull, 0ull, 0ull};
        #pragma unroll
        for (int e = 0; e < DEG; e++) {
            const uint2 d = ed[e];                       // LDS.64, half-warp broadcast
            const uint4 v = __ldg(gFeat16 + (size_t)d.x * 16 + s);
            unsigned long long w2;
            asm("mov.b64 %0, {%1, %1};" : "=l"(w2) : "r"(d.y));
            fma2_h2(acc[0], w2, v.x);
            fma2_h2(acc[1], w2, v.y);
            fma2_h2(acc[2], w2, v.z);
            fma2_h2(acc[3], w2, v.w);
        }

        float f[8];
        unpack64(acc[0], f[0], f[1]);
        unpack64(acc[1], f[2], f[3]);
        unpack64(acc[2], f[4], f[5]);
        unpack64(acc[3], f[6], f[7]);
        const __half2 p0 = __floats2half2_rn(f[0], f[1]);
        const __half2 p1 = __floats2half2_rn(f[2], f[3]);
        const __half2 p2 = __floats2half2_rn(f[4], f[5]);
        const __half2 p3 = __floats2half2_rn(f[6], f[7]);

        *(uint4*)(smem + SM_A + a_off(row, s)) =
            make_uint4(*(const unsigned*)&p0, *(const unsigned*)&p1,
                       *(const unsigned*)&p2, *(const unsigned*)&p3);
    }
    __syncthreads();

    // ---- Phase 2: warp = 16 rows x 128 cols, as two 16x64 half-tiles ----
    const int m0 = wid * 16;
    const int mi = lane >> 3;
    const int mr = lane & 7;
    const int arow = m0 + ((mi & 1) << 3) + mr;
    const uint32_t sA = smem_u32(smem + SM_A);
    const int bq = (lane >> 2) * 4 + (lane & 3);

    const int r0 = node0 + m0 + (lane >> 2);
    const int cb = 2 * (lane & 3);

    #pragma unroll
    for (int half = 0; half < 2; half++) {
        float acc[8][4];
        #pragma unroll
        for (int nc = 0; nc < 8; nc++)
            acc[nc][0] = acc[nc][1] = acc[nc][2] = acc[nc][3] = 0.f;

        #pragma unroll
        for (int kc = 0; kc < 8; kc++) {
            const int chunk = kc * 2 + (mi >> 1);
            const uint32_t aaddr = (uint32_t)a_off(arow, chunk);
            uint32_t a0, a1, a2, a3;
            ldmatrix_x4(a0, a1, a2, a3, sA + aaddr);

            const uint4* __restrict__ bp = gB + kc * 512 + half * 256 + bq;
            #pragma unroll
            for (int nc = 0; nc < 8; nc++) {
                const uint4 v = __ldg(bp + nc * 32);
                mma_f16(acc[nc][0], acc[nc][1], acc[nc][2], acc[nc][3],
                        a0, a1, a2, a3, v.x, v.y);
                mma_f16(acc[nc][0], acc[nc][1], acc[nc][2], acc[nc][3],
                        a0, a1, a2, a3, v.z, v.w);
            }
        }

        // ---- epilogue for this half: bias + relu + store ----
        #pragma unroll
        for (int nc = 0; nc < 8; nc++) {
            const int col = half * 64 + nc * 8 + cb;
            const float2 bv = __ldg((const float2*)(bias + col));
            if (r0 < N) {
                float2 o0;
                o0.x = fmaxf(acc[nc][0] + bv.x, 0.f);
                o0.y = fmaxf(acc[nc][1] + bv.y, 0.f);
                *(float2*)(out + (size_t)r0 * DD + col) = o0;
            }
            if (r0 + 8 < N) {
                float2 o1;
                o1.x = fmaxf(acc[nc][2] + bv.x, 0.f);
                o1.y = fmaxf(acc[nc][3] + bv.y, 0.f);
                *(float2*)(out + (size_t)(r0 + 8) * DD + col) = o1;
            }
        }
    }
}

extern "C" void kernel_launch(void* const* d_in, const int* in_sizes, int n_in,
                              void* d_out, int out_size)
{
    const float* feat = (const float*)d_in[0];
    const int*   rows = (const int*)d_in[1];
    const char*  cols = (const char*)d_in[2];
    const float* ew   = (const float*)d_in[3];
    const float* Wg   = (const float*)d_in[4];
    const float* bias = (const float*)d_in[5];
    float*       out  = (float*)d_out;

    const int N = in_sizes[0] / DD;

    const int total16   = N * DD / 16;
    const int nblk_feat = (total16 + 255) / 256;
    const int nblk_w    = (8 * 128 * 4 + 255) / 256;
    const int nblk_e    = (N + 63) / 64;
    prep_all<<<nblk_feat + nblk_w + nblk_e, 256>>>(feat, Wg, rows, cols, ew,
                                                   nblk_feat, nblk_w, total16, N);

    cudaFuncSetAttribute(gcn_mma, cudaFuncAttributeMaxDynamicSharedMemorySize, SM_TOTAL);
    gcn_mma<<<(N + NPB - 1) / NPB, THREADS, SM_TOTAL>>>(bias, out, N);
}